// round 1
// baseline (speedup 1.0000x reference)
#include <cuda_runtime.h>
#include <math.h>

#define BSZ  2
#define NPT  8192
#define CH   64
#define H_   64
#define W_   160
#define NPIX (H_*W_)        // 10240
#define NS   8              // point slices
#define SLICE (NPT/NS)      // 1024
#define PXB  8              // pixels per MLP block

// Scratch (static device memory; no allocations allowed)
__device__ float4 g_pts[BSZ*NPT];              // (ux, uy, Su, 0)
__device__ float  g_f3dT[BSZ*NPT*CH];          // feat_3d transposed [b][n][c]
__device__ float  g_pd[BSZ*NS*NPIX*3];         // partial top-3 d2
__device__ int    g_pi[BSZ*NS*NPIX*3];         // partial top-3 idx

// ---------------- K0a: point prep ----------------
__global__ void prep_pts(const float* __restrict__ uv) {
    int i = blockIdx.x*blockDim.x + threadIdx.x;
    if (i >= BSZ*NPT) return;
    int b = i / NPT, n = i % NPT;
    float ux = uv[(b*2+0)*NPT + n];
    float uy = uv[(b*2+1)*NPT + n];
    // match jnp.sum(uv*uv, axis=1): separate rn squares + rn add (no fma)
    float su = __fadd_rn(__fmul_rn(ux,ux), __fmul_rn(uy,uy));
    g_pts[i] = make_float4(ux, uy, su, 0.f);
}

// ---------------- K0b: transpose feat_3d [b][c][n] -> [b][n][c] ----------------
__global__ void prep_t(const float* __restrict__ f3d) {
    __shared__ float tile[32][33];
    int b = blockIdx.z;
    int n0 = blockIdx.x*32, c0 = blockIdx.y*32;
    int tx = threadIdx.x, ty = threadIdx.y;   // 32 x 8
    #pragma unroll
    for (int i = 0; i < 32; i += 8)
        tile[ty+i][tx] = f3d[((long)b*CH + c0+ty+i)*NPT + n0+tx];
    __syncthreads();
    #pragma unroll
    for (int i = 0; i < 32; i += 8)
        g_f3dT[((long)b*NPT + n0+ty+i)*CH + c0+tx] = tile[tx][ty+i];
}

// ---------------- K1: brute-force KNN over a point slice ----------------
// grid: (10 pixel tiles [5x x 2y of 32x32 px], NS slices, BSZ). 256 threads.
// Each thread owns 4 pixels in one column (shared gx => shared gx*ux product).
__global__ void __launch_bounds__(256) knn_kernel() {
    __shared__ float4 sp[SLICE];
    int tileX = blockIdx.x % 5, tileY = blockIdx.x / 5;
    int s = blockIdx.y, b = blockIdx.z;
    int t = threadIdx.x;

    const float4* src = &g_pts[b*NPT + s*SLICE];
    for (int i = t; i < SLICE; i += 256) sp[i] = src[i];
    __syncthreads();

    int cx = t & 31, ry = t >> 5;
    int gx = tileX*32 + cx;
    int gy0 = tileY*32 + ry*4;
    float gxf = (float)gx;

    float gyf[4], sg[4];
    float bd[4][3]; int bi[4][3];
    #pragma unroll
    for (int j = 0; j < 4; j++) {
        int gy = gy0 + j;
        gyf[j] = (float)gy;
        sg[j]  = (float)(gx*gx + gy*gy);   // exact: integers < 2^24
        bd[j][0]=bd[j][1]=bd[j][2]=3.4e38f;
        bi[j][0]=bi[j][1]=bi[j][2]=0;
    }

    int n0 = s*SLICE;
    for (int p = 0; p < SLICE; p++) {
        float4 pt = sp[p];
        float m = __fmul_rn(gxf, pt.x);            // rn(gx*ux), shared over 4 px
        #pragma unroll
        for (int j = 0; j < 4; j++) {
            float dot = __fmaf_rn(gyf[j], pt.y, m);          // fma(gy,uy, rn(gx*ux))
            float t1  = __fadd_rn(sg[j], pt.z);              // rn(Sg + Su)
            float d2  = __fmaf_rn(-2.f, dot, t1);            // rn(t1 - 2*dot), 2*dot exact
            if (d2 < bd[j][2]) {                             // strict < : lowest-index ties
                int idx = n0 + p;
                if (d2 < bd[j][1]) {
                    bd[j][2]=bd[j][1]; bi[j][2]=bi[j][1];
                    if (d2 < bd[j][0]) { bd[j][1]=bd[j][0]; bi[j][1]=bi[j][0];
                                         bd[j][0]=d2; bi[j][0]=idx; }
                    else               { bd[j][1]=d2; bi[j][1]=idx; }
                } else                 { bd[j][2]=d2; bi[j][2]=idx; }
            }
        }
    }

    #pragma unroll
    for (int j = 0; j < 4; j++) {
        int q = (gy0+j)*W_ + gx;
        long base = ((long)(b*NS+s)*NPIX + q)*3;
        #pragma unroll
        for (int r = 0; r < 3; r++) { g_pd[base+r]=bd[j][r]; g_pi[base+r]=bi[j][r]; }
    }
}

// ---------------- K2: merge slices + MLP + w3 GEMV ----------------
// 512 threads, 8 pixels/block: thread = (px = t>>6, channel = t&63)
__global__ void __launch_bounds__(512) mlp_kernel(
    const float* __restrict__ w1, const float* __restrict__ b1,
    const float* __restrict__ w2, const float* __restrict__ b2,
    const float* __restrict__ w3, const float* __restrict__ b3,
    float* __restrict__ out)
{
    __shared__ float s_w1[48], s_b1[16], s_w2[64*17], s_b2[64];
    __shared__ float s_w3[64*65], s_b3[64];
    __shared__ int   s_idx[PXB][3];
    __shared__ float s_si[PXB][3][3];    // [px][k][{ox,oy,norm}]
    __shared__ float s_h1[PXB][48];      // [px][o*3+k]
    __shared__ float s_fin[PXB][65];     // padded

    int t = threadIdx.x;
    int blk = blockIdx.x;
    int b  = blk / (NPIX/PXB);
    int q0 = (blk % (NPIX/PXB)) * PXB;

    for (int i = t; i < 48;    i += 512) s_w1[i] = w1[i];
    for (int i = t; i < 16;    i += 512) s_b1[i] = b1[i];
    for (int i = t; i < 64*16; i += 512) s_w2[(i/16)*17 + (i%16)] = w2[i];
    for (int i = t; i < 64;    i += 512) s_b2[i] = b2[i];
    for (int i = t; i < 64*64; i += 512) s_w3[(i/64)*65 + (i%64)] = w3[i];
    for (int i = t; i < 64;    i += 512) s_b3[i] = b3[i];

    int px = t >> 6, lane = t & 63;
    int q = q0 + px;
    int gx = q % W_, gy = q / W_;

    // Phase A1: per-pixel leader merges NS partial triples (slice order = index order)
    if (lane == 0) {
        float bd0=3.4e38f, bd1=3.4e38f, bd2=3.4e38f;
        int   i0=0, i1=0, i2=0;
        for (int s = 0; s < NS; s++) {
            long base = ((long)(b*NS+s)*NPIX + q)*3;
            #pragma unroll
            for (int r = 0; r < 3; r++) {
                float d = g_pd[base+r]; int id = g_pi[base+r];
                if (d < bd2) {
                    if (d < bd1) { bd2=bd1; i2=i1;
                        if (d < bd0) { bd1=bd0; i1=i0; bd0=d; i0=id; }
                        else         { bd1=d; i1=id; }
                    } else          { bd2=d; i2=id; }
                }
            }
        }
        int ids[3] = {i0, i1, i2};
        #pragma unroll
        for (int k = 0; k < 3; k++) {
            s_idx[px][k] = ids[k];
            float4 p = g_pts[b*NPT + ids[k]];
            float ox = p.x - (float)gx;
            float oy = p.y - (float)gy;
            float nm = sqrtf(__fadd_rn(__fmul_rn(ox,ox), __fmul_rn(oy,oy)));
            s_si[px][k][0]=ox; s_si[px][k][1]=oy; s_si[px][k][2]=nm;
        }
    }
    __syncthreads();

    // Phase A2: h1 = relu(w1 @ score_in + b1), 48 values per pixel
    if (lane < 48) {
        int o = lane / 3, k = lane % 3;
        float acc = s_b1[o];
        #pragma unroll
        for (int c = 0; c < 3; c++) acc = fmaf(s_w1[o*3+c], s_si[px][k][c], acc);
        s_h1[px][o*3+k] = fmaxf(acc, 0.f);
    }
    __syncthreads();

    // Phase B: score = sigmoid(w2 @ h1 + b2); final = sum_k score * f3d[knn]
    {
        int c = lane;
        float a0 = s_b2[c], a1 = a0, a2 = a0;
        #pragma unroll
        for (int j = 0; j < 16; j++) {
            float wv = s_w2[c*17+j];
            a0 = fmaf(wv, s_h1[px][j*3+0], a0);
            a1 = fmaf(wv, s_h1[px][j*3+1], a1);
            a2 = fmaf(wv, s_h1[px][j*3+2], a2);
        }
        float sc0 = 1.f/(1.f+expf(-a0));
        float sc1 = 1.f/(1.f+expf(-a1));
        float sc2 = 1.f/(1.f+expf(-a2));
        float f0 = g_f3dT[((long)b*NPT + s_idx[px][0])*CH + c];
        float f1 = g_f3dT[((long)b*NPT + s_idx[px][1])*CH + c];
        float f2 = g_f3dT[((long)b*NPT + s_idx[px][2])*CH + c];
        s_fin[px][c] = sc0*f0 + sc1*f1 + sc2*f2;
    }
    __syncthreads();

    // Phase C: out = relu(w3 @ final + b3); coalesced writes (8 consecutive q per o)
    {
        int o = t >> 3, p2 = t & 7;
        float acc = s_b3[o];
        #pragma unroll
        for (int c = 0; c < 64; c++) acc = fmaf(s_w3[o*65+c], s_fin[p2][c], acc);
        int qq = q0 + p2;
        out[((long)b*CH + o)*NPIX + qq] = fmaxf(acc, 0.f);
    }
}

extern "C" void kernel_launch(void* const* d_in, const int* in_sizes, int n_in,
                              void* d_out, int out_size) {
    const float* uv  = (const float*)d_in[0];
    // d_in[1] = feat_2d : unused by the reference computation
    const float* f3d = (const float*)d_in[2];
    const float* w1  = (const float*)d_in[3];
    const float* b1  = (const float*)d_in[4];
    const float* w2  = (const float*)d_in[5];
    const float* b2  = (const float*)d_in[6];
    const float* w3  = (const float*)d_in[7];
    const float* b3  = (const float*)d_in[8];
    float* out = (float*)d_out;

    prep_pts<<<(BSZ*NPT + 255)/256, 256>>>(uv);
    prep_t<<<dim3(NPT/32, CH/32, BSZ), dim3(32,8)>>>(f3d);
    knn_kernel<<<dim3(10, NS, BSZ), 256>>>();
    mlp_kernel<<<BSZ*NPIX/PXB, 512>>>(w1, b1, w2, b2, w3, b3, out);
}

// round 2
// speedup vs baseline: 2.5899x; 2.5899x over previous
#include <cuda_runtime.h>
#include <math.h>

#define BSZ  2
#define NPT  8192
#define CH   64
#define H_   64
#define W_   160
#define NPIX (H_*W_)        // 10240
#define CSZ  4              // cell size in pixels
#define CX   (W_/CSZ)       // 40
#define CY   (H_/CSZ)       // 16
#define NC   (CX*CY)        // 640
#define PXB  8              // pixels per MLP block

// Static scratch (no allocations allowed)
__device__ float4 g_ptp[BSZ*NPT];        // (ux, uy, Su, idx-bits)
__device__ int    g_cellid[BSZ*NPT];
__device__ int    g_cnt[BSZ*NC];
__device__ int    g_start[BSZ*(NC+1)];
__device__ int    g_cur[BSZ*NC];
__device__ float4 g_bin[BSZ*NPT];        // points sorted by cell
__device__ float4 g_si[BSZ*NPIX*3];      // (ox, oy, norm, idx-bits) per pixel,k
__device__ float  g_f3dT[BSZ*NPT*CH];    // feat_3d transposed [b][n][c]

// ---------------- bin build ----------------
__global__ void k_zero() {
    int i = blockIdx.x*blockDim.x + threadIdx.x;
    if (i < BSZ*NC) g_cnt[i] = 0;
}

__global__ void k_count(const float* __restrict__ uv) {
    int i = blockIdx.x*blockDim.x + threadIdx.x;
    if (i >= BSZ*NPT) return;
    int b = i / NPT, n = i % NPT;
    float ux = uv[(b*2+0)*NPT + n];
    float uy = uv[(b*2+1)*NPT + n];
    // match jnp.sum(uv*uv, axis=1): rn squares + rn add (no fma)
    float su = __fadd_rn(__fmul_rn(ux,ux), __fmul_rn(uy,uy));
    g_ptp[i] = make_float4(ux, uy, su, __int_as_float(n));
    int cx = min((int)(ux * 0.25f), CX-1);   // *0.25 is exact (pow2)
    int cy = min((int)(uy * 0.25f), CY-1);
    int cell = cy*CX + cx;
    g_cellid[i] = cell;
    atomicAdd(&g_cnt[b*NC + cell], 1);
}

__global__ void k_scan() {   // one block per batch, 1024 threads
    __shared__ int s[1024];
    int b = blockIdx.x, c = threadIdx.x;
    int v = (c < NC) ? g_cnt[b*NC + c] : 0;
    s[c] = v;
    __syncthreads();
    #pragma unroll
    for (int off = 1; off < 1024; off <<= 1) {
        int t = (c >= off) ? s[c-off] : 0;
        __syncthreads();
        s[c] += t;
        __syncthreads();
    }
    if (c < NC) {
        int st = s[c] - v;                    // exclusive
        g_start[b*(NC+1) + c] = st;
        g_cur[b*NC + c] = st;
    }
    if (c == 0) g_start[b*(NC+1) + NC] = NPT;
}

__global__ void k_scatter() {
    int i = blockIdx.x*blockDim.x + threadIdx.x;
    if (i >= BSZ*NPT) return;
    int b = i / NPT;
    int cell = g_cellid[i];
    int pos = atomicAdd(&g_cur[b*NC + cell], 1);
    g_bin[b*NPT + pos] = g_ptp[i];
}

// ---------------- transpose feat_3d [b][c][n] -> [b][n][c] ----------------
__global__ void k_transpose(const float* __restrict__ f3d) {
    __shared__ float tile[32][33];
    int b = blockIdx.z;
    int n0 = blockIdx.x*32, c0 = blockIdx.y*32;
    int tx = threadIdx.x, ty = threadIdx.y;   // 32 x 8
    #pragma unroll
    for (int i = 0; i < 32; i += 8)
        tile[ty+i][tx] = f3d[((long)b*CH + c0+ty+i)*NPT + n0+tx];
    __syncthreads();
    #pragma unroll
    for (int i = 0; i < 32; i += 8)
        g_f3dT[((long)b*NPT + n0+ty+i)*CH + c0+tx] = tile[tx][ty+i];
}

// ---------------- KNN query: ring expansion over cells ----------------
__device__ __forceinline__ void scan_pts(
    const float4* __restrict__ bin, int lo, int hi,
    float gxf, float gyf, float sg,
    float& bd0, float& bd1, float& bd2,
    int& bi0, int& bi1, int& bi2)
{
    for (int i = lo; i < hi; i++) {
        float4 p = bin[i];
        int idx = __float_as_int(p.w);
        float m   = __fmul_rn(gxf, p.x);            // rn(gx*ux)
        float dot = __fmaf_rn(gyf, p.y, m);         // fma(gy,uy, m)
        float t1  = __fadd_rn(sg, p.z);             // rn(Sg + Su)
        float d2  = __fmaf_rn(-2.f, dot, t1);       // rn(t1 - 2*dot)
        // lexicographic (d2, idx): independent of scatter order, matches top_k stability
        if (d2 < bd2 || (d2 == bd2 && idx < bi2)) {
            bool l1 = (d2 < bd1) || (d2 == bd1 && idx < bi1);
            bool l0 = (d2 < bd0) || (d2 == bd0 && idx < bi0);
            if (l0)      { bd2=bd1; bi2=bi1; bd1=bd0; bi1=bi0; bd0=d2; bi0=idx; }
            else if (l1) { bd2=bd1; bi2=bi1; bd1=d2;  bi1=idx; }
            else         { bd2=d2;  bi2=idx; }
        }
    }
}

__global__ void __launch_bounds__(128) k_query() {
    int pid = blockIdx.x*blockDim.x + threadIdx.x;
    if (pid >= BSZ*NPIX) return;
    int b = pid / NPIX, q = pid % NPIX;
    int gx = q % W_, gy = q / W_;
    float gxf = (float)gx, gyf = (float)gy;
    float sg = (float)(gx*gx + gy*gy);              // exact (< 2^24)

    float bd0 = 3.4e38f, bd1 = 3.4e38f, bd2 = 3.4e38f;
    int   bi0 = 0x7fffffff, bi1 = 0x7fffffff, bi2 = 0x7fffffff;

    int cx = gx >> 2, cy = gy >> 2;
    const float4* bin = &g_bin[b*NPT];
    const int*    st  = &g_start[b*(NC+1)];

    for (int r = 0; r < 64; r++) {
        int x0 = max(cx-r, 0), x1 = min(cx+r, CX-1);
        int y0 = max(cy-r, 0), y1 = min(cy+r, CY-1);
        for (int yy = y0; yy <= y1; yy++) {
            if (yy == cy-r || yy == cy+r) {
                // full row span: cells contiguous in memory -> one range
                scan_pts(bin, st[yy*CX + x0], st[yy*CX + x1 + 1],
                         gxf, gyf, sg, bd0, bd1, bd2, bi0, bi1, bi2);
            } else {
                if (cx-r >= 0)
                    scan_pts(bin, st[yy*CX + (cx-r)], st[yy*CX + (cx-r) + 1],
                             gxf, gyf, sg, bd0, bd1, bd2, bi0, bi1, bi2);
                if (cx+r <= CX-1)
                    scan_pts(bin, st[yy*CX + (cx+r)], st[yy*CX + (cx+r) + 1],
                             gxf, gyf, sg, bd0, bd1, bd2, bi0, bi1, bi2);
            }
        }
        // unscanned points have exact dist >= 4r -> rounded d2 >= (4r)^2 - ~0.01
        if (r >= 1) {
            float bound = (float)(16*r*r) - 1.0f;
            if (bd2 < bound) break;
        }
        if (x0 == 0 && y0 == 0 && x1 == CX-1 && y1 == CY-1) break;
    }

    int ids[3] = {bi0, bi1, bi2};
    #pragma unroll
    for (int k = 0; k < 3; k++) {
        float4 p = g_ptp[b*NPT + ids[k]];
        float ox = p.x - gxf;
        float oy = p.y - gyf;
        float nm = sqrtf(__fadd_rn(__fmul_rn(ox,ox), __fmul_rn(oy,oy)));
        g_si[((long)(b*NPIX) + q)*3 + k] = make_float4(ox, oy, nm, p.w);
    }
}

// ---------------- MLP + w3 GEMV ----------------
__global__ void __launch_bounds__(512) k_mlp(
    const float* __restrict__ w1, const float* __restrict__ b1,
    const float* __restrict__ w2, const float* __restrict__ b2,
    const float* __restrict__ w3, const float* __restrict__ b3,
    float* __restrict__ out)
{
    __shared__ float s_w1[48], s_b1[16], s_w2[64*17], s_b2[64];
    __shared__ float s_w3[64*68], s_b3[64];          // pad 68: 16B-aligned rows
    __shared__ float4 s_si[PXB*3];                   // (ox,oy,norm,idx)
    __shared__ float s_h1[PXB][48];
    __shared__ float s_fin[PXB][68];

    int t = threadIdx.x;
    int blk = blockIdx.x;
    int b  = blk / (NPIX/PXB);
    int q0 = (blk % (NPIX/PXB)) * PXB;

    for (int i = t; i < 48;    i += 512) s_w1[i] = w1[i];
    for (int i = t; i < 16;    i += 512) s_b1[i] = b1[i];
    for (int i = t; i < 64*16; i += 512) s_w2[(i/16)*17 + (i%16)] = w2[i];
    for (int i = t; i < 64;    i += 512) { s_b2[i] = b2[i]; s_b3[i] = b3[i]; }
    // w3 via float4: 1024 vec4 loads, 2 per thread
    for (int i = t; i < 1024; i += 512) {
        float4 v = ((const float4*)w3)[i];
        int row = i >> 4, c4 = (i & 15) << 2;
        *(float4*)&s_w3[row*68 + c4] = v;
    }
    if (t < PXB*3)
        s_si[t] = g_si[((long)(b*NPIX) + q0)*3 + t];
    __syncthreads();

    int px = t >> 6, lane = t & 63;
    // Phase A: h1 = relu(w1 @ [ox,oy,norm] + b1)
    if (lane < 48) {
        int o = lane / 3, k = lane % 3;
        float4 si = s_si[px*3 + k];
        float acc = s_b1[o];
        acc = fmaf(s_w1[o*3+0], si.x, acc);
        acc = fmaf(s_w1[o*3+1], si.y, acc);
        acc = fmaf(s_w1[o*3+2], si.z, acc);
        s_h1[px][o*3+k] = fmaxf(acc, 0.f);
    }
    __syncthreads();

    // Phase B: score = sigmoid(w2 @ h1 + b2); fin = sum_k score_k * f3d[idx_k]
    {
        int c = lane;
        float a0 = s_b2[c], a1 = a0, a2 = a0;
        #pragma unroll
        for (int j = 0; j < 16; j++) {
            float wv = s_w2[c*17+j];
            a0 = fmaf(wv, s_h1[px][j*3+0], a0);
            a1 = fmaf(wv, s_h1[px][j*3+1], a1);
            a2 = fmaf(wv, s_h1[px][j*3+2], a2);
        }
        float sc0 = __fdividef(1.f, 1.f + __expf(-a0));
        float sc1 = __fdividef(1.f, 1.f + __expf(-a1));
        float sc2 = __fdividef(1.f, 1.f + __expf(-a2));
        int i0 = __float_as_int(s_si[px*3+0].w);
        int i1 = __float_as_int(s_si[px*3+1].w);
        int i2 = __float_as_int(s_si[px*3+2].w);
        float f0 = g_f3dT[((long)b*NPT + i0)*CH + c];
        float f1 = g_f3dT[((long)b*NPT + i1)*CH + c];
        float f2 = g_f3dT[((long)b*NPT + i2)*CH + c];
        s_fin[px][c] = sc0*f0 + sc1*f1 + sc2*f2;
    }
    __syncthreads();

    // Phase C: out = relu(w3 @ fin + b3), vectorized LDS.128, coalesced writes
    {
        int o = t >> 3, p2 = t & 7;
        float acc = s_b3[o];
        #pragma unroll
        for (int c = 0; c < 64; c += 4) {
            float4 wv = *(const float4*)&s_w3[o*68 + c];
            float4 fv = *(const float4*)&s_fin[p2][c];
            acc = fmaf(wv.x, fv.x, acc);
            acc = fmaf(wv.y, fv.y, acc);
            acc = fmaf(wv.z, fv.z, acc);
            acc = fmaf(wv.w, fv.w, acc);
        }
        out[((long)(b*CH) + o)*NPIX + q0 + p2] = fmaxf(acc, 0.f);
    }
}

extern "C" void kernel_launch(void* const* d_in, const int* in_sizes, int n_in,
                              void* d_out, int out_size) {
    const float* uv  = (const float*)d_in[0];
    // d_in[1] = feat_2d : unused by the reference computation
    const float* f3d = (const float*)d_in[2];
    const float* w1  = (const float*)d_in[3];
    const float* b1  = (const float*)d_in[4];
    const float* w2  = (const float*)d_in[5];
    const float* b2  = (const float*)d_in[6];
    const float* w3  = (const float*)d_in[7];
    const float* b3  = (const float*)d_in[8];
    float* out = (float*)d_out;

    k_zero<<<(BSZ*NC + 255)/256, 256>>>();
    k_count<<<(BSZ*NPT + 255)/256, 256>>>(uv);
    k_scan<<<BSZ, 1024>>>();
    k_scatter<<<(BSZ*NPT + 255)/256, 256>>>();
    k_transpose<<<dim3(NPT/32, CH/32, BSZ), dim3(32,8)>>>(f3d);
    k_query<<<(BSZ*NPIX + 127)/128, 128>>>();
    k_mlp<<<BSZ*NPIX/PXB, 512>>>(w1, b1, w2, b2, w3, b3, out);
}

// round 3
// speedup vs baseline: 2.6591x; 1.0267x over previous
#include <cuda_runtime.h>
#include <math.h>

#define BSZ  2
#define NPT  8192
#define CH   64
#define H_   64
#define W_   160
#define NPIX (H_*W_)        // 10240
#define CSZ  4
#define CX   (W_/CSZ)       // 40
#define CY   (H_/CSZ)       // 16
#define NC   (CX*CY)        // 640
#define CAND_MAX 640

// Static scratch
__device__ float4 g_ptp[BSZ*NPT];        // (ux, uy, Su, idx-bits) in original order
__device__ float4 g_bin[BSZ*NPT];        // points sorted by cell
__device__ int    g_start[BSZ*(NC+1)];
__device__ float  g_f3dT[BSZ*NPT*CH];    // feat_3d transposed [b][n][c]

// ---------------- helpers ----------------
__device__ __forceinline__ float d2of(float4 p, float gxf, float gyf, float sg) {
    float m   = __fmul_rn(gxf, p.x);            // rn(gx*ux)
    float dot = __fmaf_rn(gyf, p.y, m);         // fma(gy,uy, m)
    float t1  = __fadd_rn(sg, p.z);             // rn(Sg + Su)
    return __fmaf_rn(-2.f, dot, t1);            // rn(t1 - 2*dot)
}

__device__ __forceinline__ void ins3(float d2, int idx,
    float& bd0, float& bd1, float& bd2, int& bi0, int& bi1, int& bi2) {
    if (d2 < bd2 || (d2 == bd2 && idx < bi2)) {
        bool l1 = (d2 < bd1) || (d2 == bd1 && idx < bi1);
        bool l0 = (d2 < bd0) || (d2 == bd0 && idx < bi0);
        if (l0)      { bd2=bd1; bi2=bi1; bd1=bd0; bi1=bi0; bd0=d2; bi0=idx; }
        else if (l1) { bd2=bd1; bi2=bi1; bd1=d2;  bi1=idx; }
        else         { bd2=d2;  bi2=idx; }
    }
}

// ---------------- K1: fat prep kernel: binning (blocks 0..1) + transpose ----------------
__global__ void __launch_bounds__(1024) k_prep(const float* __restrict__ uv,
                                               const float* __restrict__ f3d) {
    __shared__ int s_cnt[NC];
    __shared__ int s_scan[1024];
    __shared__ int s_curc[NC];
    __shared__ float tile[32][33];

    int t = threadIdx.x;
    if (blockIdx.x < BSZ) {
        // ---- binning: whole batch in one block ----
        int b = blockIdx.x;
        for (int i = t; i < NC; i += 1024) s_cnt[i] = 0;
        __syncthreads();
        float ux[8], uy[8], su[8]; int cl[8];
        #pragma unroll
        for (int k = 0; k < 8; k++) {
            int n = t + k*1024;
            ux[k] = uv[(b*2+0)*NPT + n];
            uy[k] = uv[(b*2+1)*NPT + n];
            // match jnp.sum(uv*uv): rn squares + rn add (no fma)
            su[k] = __fadd_rn(__fmul_rn(ux[k],ux[k]), __fmul_rn(uy[k],uy[k]));
            int cx = min((int)(ux[k]*0.25f), CX-1);
            int cy = min((int)(uy[k]*0.25f), CY-1);
            cl[k] = cy*CX + cx;
            g_ptp[b*NPT + n] = make_float4(ux[k], uy[k], su[k], __int_as_float(n));
            atomicAdd(&s_cnt[cl[k]], 1);
        }
        __syncthreads();
        int v = (t < NC) ? s_cnt[t] : 0;
        s_scan[t] = v;
        __syncthreads();
        #pragma unroll
        for (int off = 1; off < 1024; off <<= 1) {
            int tmp = (t >= off) ? s_scan[t-off] : 0;
            __syncthreads();
            s_scan[t] += tmp;
            __syncthreads();
        }
        if (t < NC) { int st0 = s_scan[t] - v; g_start[b*(NC+1)+t] = st0; s_curc[t] = st0; }
        if (t == 0) g_start[b*(NC+1)+NC] = NPT;
        __syncthreads();
        #pragma unroll
        for (int k = 0; k < 8; k++) {
            int n = t + k*1024;
            int pos = atomicAdd(&s_curc[cl[k]], 1);
            g_bin[b*NPT + pos] = make_float4(ux[k], uy[k], su[k], __int_as_float(n));
        }
    } else {
        // ---- transpose feat_3d [b][c][n] -> [b][n][c] ----
        int bid = blockIdx.x - BSZ;           // 0..1023
        int nt = bid & 255;
        int ct = (bid >> 8) & 1;
        int b  = bid >> 9;
        int tx = t & 31, ty = t >> 5;
        int n0 = nt*32, c0 = ct*32;
        tile[ty][tx] = f3d[((long)b*CH + c0+ty)*NPT + n0+tx];
        __syncthreads();
        g_f3dT[((long)b*NPT + n0+ty)*CH + c0+tx] = tile[tx][ty];
    }
}

// ---------------- K2: fused query + MLP, one block per cell (16 pixels) ----------------
__global__ void __launch_bounds__(512) k_main(
    const float* __restrict__ w1, const float* __restrict__ b1,
    const float* __restrict__ w2, const float* __restrict__ b2,
    const float* __restrict__ w3, const float* __restrict__ b3,
    float* __restrict__ out)
{
    __shared__ float s_w1[48], s_b1[16], s_w2[64*17], s_b2[64];
    __shared__ float s_w3[64*68], s_b3[64];
    __shared__ float4 s_cand[CAND_MAX];
    __shared__ int s_rlo[3], s_rhi[3], s_nc;
    __shared__ float s_td[16][24];
    __shared__ int   s_ti[16][24];
    __shared__ float4 s_si[16][3];          // (ox,oy,norm,idx-bits)
    __shared__ float s_h1[16][48];
    __shared__ float s_fin[16][68];

    int t = threadIdx.x;
    int b = blockIdx.x / NC, cell = blockIdx.x % NC;
    int cx = cell % CX, cy = cell / CX;

    // ---- weight prefetch (independent of query; LDGs overlap the scan) ----
    for (int i = t; i < 48;   i += 512) s_w1[i] = w1[i];
    for (int i = t; i < 16;   i += 512) s_b1[i] = b1[i];
    for (int i = t; i < 1024; i += 512) s_w2[(i>>4)*17 + (i&15)] = w2[i];
    for (int i = t; i < 64;   i += 512) { s_b2[i] = b2[i]; s_b3[i] = b3[i]; }
    for (int i = t; i < 1024; i += 512) {
        float4 v = ((const float4*)w3)[i];
        *(float4*)&s_w3[(i>>4)*68 + ((i&15)<<2)] = v;
    }

    const int*    st  = &g_start[b*(NC+1)];
    const float4* bin = &g_bin[b*NPT];

    // ---- candidate ranges: 3x3 cells (rings 0..1), rows contiguous ----
    if (t == 0) {
        int y0 = max(cy-1,0), y1 = min(cy+1,CY-1);
        int xlo = max(cx-1,0), xhi = min(cx+1,CX-1);
        int n = 0, tot = 0;
        for (int yy = y0; yy <= y1; yy++) {
            int lo = st[yy*CX + xlo], hi = st[yy*CX + xhi + 1];
            s_rlo[n] = lo; s_rhi[n] = hi; tot += hi - lo; n++;
        }
        for (; n < 3; n++) { s_rlo[n] = 0; s_rhi[n] = 0; }
        s_nc = tot;
    }
    __syncthreads();
    int ncand = s_nc;
    bool small = (ncand <= CAND_MAX);
    if (small) {
        int off = 0;
        #pragma unroll
        for (int r = 0; r < 3; r++) {
            int lo = s_rlo[r], len = s_rhi[r] - lo;
            for (int i = t; i < len; i += 512) s_cand[off + i] = bin[lo + i];
            off += len;
        }
    }
    __syncthreads();

    // ---- parallel scan: 8 threads per pixel over smem candidates ----
    if (small && t < 128) {
        int px = t >> 3, j = t & 7;
        int gx = (cx<<2) + (px&3), gy = (cy<<2) + (px>>2);
        float gxf = (float)gx, gyf = (float)gy;
        float sg = (float)(gx*gx + gy*gy);
        float bd0=3.4e38f, bd1=3.4e38f, bd2=3.4e38f;
        int   bi0=0x7fffffff, bi1=0x7fffffff, bi2=0x7fffffff;
        for (int i = j; i < ncand; i += 8) {
            float4 p = s_cand[i];
            ins3(d2of(p, gxf, gyf, sg), __float_as_int(p.w), bd0,bd1,bd2,bi0,bi1,bi2);
        }
        s_td[px][j*3+0]=bd0; s_ti[px][j*3+0]=bi0;
        s_td[px][j*3+1]=bd1; s_ti[px][j*3+1]=bi1;
        s_td[px][j*3+2]=bd2; s_ti[px][j*3+2]=bi2;
    }
    __syncthreads();

    // ---- per-pixel leader: merge 24 triples; rare ring>=2 fallback; emit si ----
    if (t < 16) {
        int px = t;
        int gx = (cx<<2) + (px&3), gy = (cy<<2) + (px>>2);
        float gxf = (float)gx, gyf = (float)gy;
        float sg = (float)(gx*gx + gy*gy);
        float bd0=3.4e38f, bd1=3.4e38f, bd2=3.4e38f;
        int   bi0=0x7fffffff, bi1=0x7fffffff, bi2=0x7fffffff;
        if (small) {
            #pragma unroll
            for (int j = 0; j < 24; j++)
                ins3(s_td[px][j], s_ti[px][j], bd0,bd1,bd2,bi0,bi1,bi2);
        }
        int rstart = small ? 2 : 0;
        bool done = small && (bd2 < 15.f);   // unscanned dist >= 4 -> d2 >= 16 - eps
        for (int r = rstart; !done && r < 64; r++) {
            int x0 = max(cx-r,0), x1 = min(cx+r,CX-1);
            int y0 = max(cy-r,0), y1 = min(cy+r,CY-1);
            for (int yy = y0; yy <= y1; yy++) {
                if (yy == cy-r || yy == cy+r) {
                    int lo = st[yy*CX + x0], hi = st[yy*CX + x1 + 1];
                    for (int i = lo; i < hi; i++) {
                        float4 p = bin[i];
                        ins3(d2of(p,gxf,gyf,sg), __float_as_int(p.w), bd0,bd1,bd2,bi0,bi1,bi2);
                    }
                } else {
                    if (cx-r >= 0) {
                        int c0i = yy*CX + (cx-r);
                        for (int i = st[c0i]; i < st[c0i+1]; i++) {
                            float4 p = bin[i];
                            ins3(d2of(p,gxf,gyf,sg), __float_as_int(p.w), bd0,bd1,bd2,bi0,bi1,bi2);
                        }
                    }
                    if (cx+r <= CX-1) {
                        int c1i = yy*CX + (cx+r);
                        for (int i = st[c1i]; i < st[c1i+1]; i++) {
                            float4 p = bin[i];
                            ins3(d2of(p,gxf,gyf,sg), __float_as_int(p.w), bd0,bd1,bd2,bi0,bi1,bi2);
                        }
                    }
                }
            }
            if (r >= 1 && bd2 < (float)(16*r*r) - 1.f) done = true;
            if (x0==0 && y0==0 && x1==CX-1 && y1==CY-1) done = true;
        }
        int ids[3] = {bi0, bi1, bi2};
        #pragma unroll
        for (int k = 0; k < 3; k++) {
            float4 p = g_ptp[b*NPT + ids[k]];
            float ox = p.x - gxf;
            float oy = p.y - gyf;
            float nm = sqrtf(__fadd_rn(__fmul_rn(ox,ox), __fmul_rn(oy,oy)));
            s_si[px][k] = make_float4(ox, oy, nm, p.w);
        }
    }
    __syncthreads();

    // ---- Phase A: h1 = relu(w1 @ [ox,oy,norm] + b1) ----
    {
        int lane = t & 63;
        if (lane < 48) {
            #pragma unroll
            for (int it = 0; it < 2; it++) {
                int px = (t>>6) + (it<<3);
                int o = lane / 3, k = lane % 3;
                float4 si = s_si[px][k];
                float acc = s_b1[o];
                acc = fmaf(s_w1[o*3+0], si.x, acc);
                acc = fmaf(s_w1[o*3+1], si.y, acc);
                acc = fmaf(s_w1[o*3+2], si.z, acc);
                s_h1[px][o*3+k] = fmaxf(acc, 0.f);
            }
        }
    }
    __syncthreads();

    // ---- Phase B: score = sigmoid(w2 @ h1 + b2); fin = sum_k score_k * f3d[idx_k] ----
    {
        int c = t & 63;
        #pragma unroll
        for (int it = 0; it < 2; it++) {
            int px = (t>>6) + (it<<3);
            float a0 = s_b2[c], a1 = a0, a2 = a0;
            #pragma unroll
            for (int j = 0; j < 16; j++) {
                float wv = s_w2[c*17+j];
                a0 = fmaf(wv, s_h1[px][j*3+0], a0);
                a1 = fmaf(wv, s_h1[px][j*3+1], a1);
                a2 = fmaf(wv, s_h1[px][j*3+2], a2);
            }
            float sc0 = __fdividef(1.f, 1.f + __expf(-a0));
            float sc1 = __fdividef(1.f, 1.f + __expf(-a1));
            float sc2 = __fdividef(1.f, 1.f + __expf(-a2));
            int i0 = __float_as_int(s_si[px][0].w);
            int i1 = __float_as_int(s_si[px][1].w);
            int i2 = __float_as_int(s_si[px][2].w);
            float f0 = g_f3dT[((long)b*NPT + i0)*CH + c];
            float f1 = g_f3dT[((long)b*NPT + i1)*CH + c];
            float f2 = g_f3dT[((long)b*NPT + i2)*CH + c];
            s_fin[px][c] = sc0*f0 + sc1*f1 + sc2*f2;
        }
    }
    __syncthreads();

    // ---- Phase C: out = relu(w3 @ fin + b3) ----
    {
        int o = t >> 3;
        #pragma unroll
        for (int it = 0; it < 2; it++) {
            int p2 = (t&7) + (it<<3);
            float acc = s_b3[o];
            #pragma unroll
            for (int c = 0; c < 64; c += 4) {
                float4 wv = *(const float4*)&s_w3[o*68 + c];
                float4 fv = *(const float4*)&s_fin[p2][c];
                acc = fmaf(wv.x, fv.x, acc);
                acc = fmaf(wv.y, fv.y, acc);
                acc = fmaf(wv.z, fv.z, acc);
                acc = fmaf(wv.w, fv.w, acc);
            }
            int gx = (cx<<2) + (p2&3), gy = (cy<<2) + (p2>>2);
            out[((long)(b*CH) + o)*NPIX + gy*W_ + gx] = fmaxf(acc, 0.f);
        }
    }
}

extern "C" void kernel_launch(void* const* d_in, const int* in_sizes, int n_in,
                              void* d_out, int out_size) {
    const float* uv  = (const float*)d_in[0];
    // d_in[1] = feat_2d : unused by the reference computation
    const float* f3d = (const float*)d_in[2];
    const float* w1  = (const float*)d_in[3];
    const float* b1  = (const float*)d_in[4];
    const float* w2  = (const float*)d_in[5];
    const float* b2  = (const float*)d_in[6];
    const float* w3  = (const float*)d_in[7];
    const float* b3  = (const float*)d_in[8];
    float* out = (float*)d_out;

    k_prep<<<BSZ + 1024, 1024>>>(uv, f3d);
    k_main<<<BSZ*NC, 512>>>(w1, b1, w2, b2, w3, b3, out);
}